// round 14
// baseline (speedup 1.0000x reference)
#include <cuda_runtime.h>
#include <cuda_fp16.h>
#include <cstdint>
#include <math.h>

typedef __half half_t;

// Problem constants
#define B_  4
#define T_  2048
#define D_  1024
#define H_  16
#define DH_ 64
#define M_  (B_ * T_)   // 8192
#define DD_ ((size_t)D_ * D_)
#define MD_ ((size_t)M_ * D_)

// Q prescale: 1/sqrt(64) * log2(e)  (softmax done in 2^x domain)
#define QSCALE 0.18033688011110932f

// Scratch
__device__ half_t g_in3[3][MD_];   // q,k,v converted
__device__ half_t g_qkv[3][MD_];   // Q (pre-scaled), K, V
__device__ half_t g_att[MD_];      // attention output
__device__ half_t g_w4[4][DD_];    // Wq,Wk,Wv,Wo transposed [N][K]

// ============================================================================
// PTX helpers
// ============================================================================
__device__ __forceinline__ uint32_t smem_u32(const void* p) {
    uint32_t a;
    asm("{ .reg .u64 t; cvta.to.shared.u64 t, %1; cvt.u32.u64 %0, t; }" : "=r"(a) : "l"(p));
    return a;
}
__device__ __forceinline__ void mma_f16(float* d, const uint32_t* a, uint32_t b0, uint32_t b1) {
    asm volatile(
        "mma.sync.aligned.m16n8k16.row.col.f32.f16.f16.f32 "
        "{%0,%1,%2,%3}, {%4,%5,%6,%7}, {%8,%9}, {%0,%1,%2,%3};"
        : "+f"(d[0]), "+f"(d[1]), "+f"(d[2]), "+f"(d[3])
        : "r"(a[0]), "r"(a[1]), "r"(a[2]), "r"(a[3]), "r"(b0), "r"(b1));
}
__device__ __forceinline__ void ldm4(uint32_t* r, uint32_t a) {
    asm volatile("ldmatrix.sync.aligned.m8n8.x4.shared.b16 {%0,%1,%2,%3}, [%4];"
                 : "=r"(r[0]), "=r"(r[1]), "=r"(r[2]), "=r"(r[3]) : "r"(a));
}
__device__ __forceinline__ void ldm4t(uint32_t* r, uint32_t a) {
    asm volatile("ldmatrix.sync.aligned.m8n8.x4.trans.shared.b16 {%0,%1,%2,%3}, [%4];"
                 : "=r"(r[0]), "=r"(r[1]), "=r"(r[2]), "=r"(r[3]) : "r"(a));
}
__device__ __forceinline__ void cp16(uint32_t dst, const void* src) {
    asm volatile("cp.async.cg.shared.global [%0], [%1], 16;" :: "r"(dst), "l"(src));
}
#define CP_COMMIT() asm volatile("cp.async.commit_group;" ::: "memory")
#define CP_WAIT0()  asm volatile("cp.async.wait_group 0;" ::: "memory")

__device__ __forceinline__ uint32_t pkh(float a, float b) {
    __half2 t = __floats2half2_rn(a, b);
    return *reinterpret_cast<uint32_t*>(&t);
}
__device__ __forceinline__ uint32_t ex2_h2(uint32_t x) {
    uint32_t r;
    asm("ex2.approx.f16x2 %0, %1;" : "=r"(r) : "r"(x));
    return r;
}

// ============================================================================
// transpose + convert all 4 weights (grid.z selects)
// ============================================================================
__global__ __launch_bounds__(256) void transpose_cvt4(
    const float* __restrict__ W0, const float* __restrict__ W1,
    const float* __restrict__ W2, const float* __restrict__ W3,
    half_t* __restrict__ o4)
{
    __shared__ float t[32][33];
    const float* in = (blockIdx.z == 0) ? W0 : (blockIdx.z == 1) ? W1
                     : (blockIdx.z == 2) ? W2 : W3;
    half_t* o = o4 + (size_t)blockIdx.z * DD_;
    int x = blockIdx.x * 32 + threadIdx.x;
    int y0 = blockIdx.y * 32 + threadIdx.y;
#pragma unroll
    for (int i = 0; i < 32; i += 8)
        t[threadIdx.y + i][threadIdx.x] = in[(size_t)(y0 + i) * D_ + x];
    __syncthreads();
    x = blockIdx.y * 32 + threadIdx.x;
    y0 = blockIdx.x * 32 + threadIdx.y;
#pragma unroll
    for (int i = 0; i < 32; i += 8)
        o[(size_t)(y0 + i) * D_ + x] = __float2half_rn(t[threadIdx.x][threadIdx.y + i]);
}

// ============================================================================
// convert q,k,v fp32 -> fp16 in one launch (grid.y selects)
// ============================================================================
__global__ __launch_bounds__(256) void tohalf3(
    const float4* __restrict__ q, const float4* __restrict__ k,
    const float4* __restrict__ v, uint2* __restrict__ out3, int n4)
{
    int i = blockIdx.x * 256 + threadIdx.x;
    if (i >= n4) return;
    const float4* in = (blockIdx.y == 0) ? q : (blockIdx.y == 1) ? k : v;
    uint2* out = out3 + (size_t)blockIdx.y * (MD_ / 4) + i;
    float4 vv = in[i];
    uint2 o;
    o.x = pkh(vv.x, vv.y);
    o.y = pkh(vv.z, vv.w);
    *out = o;
}

// ============================================================================
// fp16 GEMM core: C[128,128 tile] = (A @ Wt^T + bias) * scale
// BK=64, 256 threads (2m x 4n warps), 2-stage cp.async, 1 sync per k-tile.
// (Proven R12 config — at the legacy-HMMA dispatch roofline.)
// ============================================================================
#define GKS 72
#define GTILE (128 * GKS)
#define G_SMEM (2 * 2 * GTILE * 2)   // 73728 bytes

__device__ __forceinline__ void gemm_core(
    const half_t* __restrict__ A, const half_t* __restrict__ Bt,
    const float* __restrict__ bias, float scale,
    float* __restrict__ outF, half_t* __restrict__ outH, half_t* sb)
{
    const uint32_t sbase = smem_u32(sb);
    const int tid = threadIdx.x, lane = tid & 31, wid = tid >> 5;
    const int wm = wid & 1, wn = wid >> 1;
    const int row0 = blockIdx.y * 128, col0 = blockIdx.x * 128;

    float d[4][4][4] = {};

    auto load_stage = [&](int s, int kt) {
        const half_t* srcs[2] = {A, Bt};
        const int rb[2] = {row0, col0};
#pragma unroll
        for (int bi = 0; bi < 2; ++bi) {
#pragma unroll
            for (int it = 0; it < 4; ++it) {
                int ch = tid + it * 256;
                int r = ch >> 3, c8 = ch & 7;
                const half_t* g = srcs[bi] + (size_t)(rb[bi] + r) * D_ + kt * 64 + c8 * 8;
                cp16(sbase + ((s * 2 + bi) * GTILE + r * GKS + c8 * 8) * 2, g);
            }
        }
    };

    auto compute_stage = [&](int s) {
        const uint32_t aB = sbase + (s * 2 + 0) * GTILE * 2;
        const uint32_t bB = sbase + (s * 2 + 1) * GTILE * 2;
        const int l15 = lane & 15, l7 = lane & 7;
        const int aro = (lane & 16) ? 8 : 0;
        const int bko = (lane & 8) ? 8 : 0;
        const int bro = (lane & 16) ? 8 : 0;
#pragma unroll
        for (int kh2 = 0; kh2 < 4; ++kh2) {
            uint32_t af[4][4], bf[2][4];
#pragma unroll
            for (int i = 0; i < 4; ++i) {
                uint32_t off = (uint32_t)((wm * 64 + i * 16 + l15) * GKS + kh2 * 16 + aro) * 2;
                ldm4(af[i], aB + off);
            }
#pragma unroll
            for (int nb = 0; nb < 2; ++nb) {
                uint32_t off = (uint32_t)((wn * 32 + nb * 16 + l7 + bro) * GKS + kh2 * 16 + bko) * 2;
                ldm4(bf[nb], bB + off);
            }
#pragma unroll
            for (int i = 0; i < 4; ++i)
#pragma unroll
                for (int j = 0; j < 4; ++j) {
                    const int nb = j >> 1, hf = (j & 1) * 2;
                    mma_f16(d[i][j], af[i], bf[nb][hf], bf[nb][hf + 1]);
                }
        }
    };

    load_stage(0, 0); CP_COMMIT();
    for (int kt = 0; kt < 16; ++kt) {
        CP_WAIT0();
        __syncthreads();
        if (kt + 1 < 16) { load_stage((kt + 1) & 1, kt + 1); CP_COMMIT(); }
        compute_stage(kt & 1);
    }

    // Epilogue
    const int lr = lane >> 2, lc = lane & 3;
#pragma unroll
    for (int i = 0; i < 4; ++i) {
        const int r0g = row0 + wm * 64 + i * 16 + lr;
#pragma unroll
        for (int j = 0; j < 4; ++j) {
            const int cg = col0 + wn * 32 + j * 8 + lc * 2;
            const float2 bb = *(const float2*)&bias[cg];
            const float v0 = (d[i][j][0] + bb.x) * scale;
            const float v1 = (d[i][j][1] + bb.y) * scale;
            const float v2 = (d[i][j][2] + bb.x) * scale;
            const float v3 = (d[i][j][3] + bb.y) * scale;
            if (outF) {
                *(float2*)&outF[(size_t)r0g * D_ + cg] = make_float2(v0, v1);
                *(float2*)&outF[(size_t)(r0g + 8) * D_ + cg] = make_float2(v2, v3);
            } else {
                *(uint32_t*)(outH + (size_t)r0g * D_ + cg) = pkh(v0, v1);
                *(uint32_t*)(outH + (size_t)(r0g + 8) * D_ + cg) = pkh(v2, v3);
            }
        }
    }
}

__global__ __launch_bounds__(256) void gemm_qkv(
    const half_t* __restrict__ in3, const half_t* __restrict__ w4,
    const float* __restrict__ b_q, const float* __restrict__ b_k,
    const float* __restrict__ b_v, half_t* __restrict__ qkv)
{
    extern __shared__ half_t sb[];
    const int z = blockIdx.z;
    const float* bias = (z == 0) ? b_q : (z == 1) ? b_k : b_v;
    const float scale = (z == 0) ? QSCALE : 1.0f;
    gemm_core(in3 + (size_t)z * MD_, w4 + (size_t)z * DD_, bias, scale,
              nullptr, qkv + (size_t)z * MD_, sb);
}

__global__ __launch_bounds__(256) void gemm_out(
    const half_t* __restrict__ att, const half_t* __restrict__ Wo,
    const float* __restrict__ b_o, float* __restrict__ out)
{
    extern __shared__ half_t sb[];
    gemm_core(att, Wo, b_o, 1.0f, out, nullptr, sb);
}

// ============================================================================
// Flash attention, fp16 mma.sync (f32 acc), static-max log2 softmax.
// WAVE-QUANTIZATION-TUNED: q-tile 64, 64 threads (2 warps x 32 q-rows,
// keeping the proven 2x K/V fragment reuse), KV staged 64 rows, smem padded
// to 40KB so exactly 5 CTAs/SM fit -> 740 slots; grid 2048 -> W=2.77 ->
// 92.3% wave utilization (vs 77% at 3 CTAs/SM with q-tile 128).
// Q pre-scaled by 0.125*log2(e) at projection time.
// ============================================================================
#define AST 72
#define ABUF64 (64 * AST)            // halves per 64-row buffer
#define A_SMEM 40960                 // 4*ABUF64*2 = 36864, padded to cap 5 CTAs/SM

__global__ __launch_bounds__(64, 5) void attn_f16(
    const half_t* __restrict__ Qg, const half_t* __restrict__ Kg,
    const half_t* __restrict__ Vg, half_t* __restrict__ Og)
{
    extern __shared__ half_t sa_[];
    const uint32_t sbase = smem_u32(sa_);
    const int tid = threadIdx.x, lane = tid & 31, wq = tid >> 5;
    const int q0 = blockIdx.x * 64, hd = blockIdx.y, bb = blockIdx.z;
    const size_t gbase = ((size_t)bb * T_) * D_ + (size_t)hd * 64;

    const int l15 = lane & 15, l7 = lane & 7;
    const int ao  = (lane & 16) ? 8 : 0;
    const int bro = (lane & 16) ? 8 : 0;
    const int bko = (lane & 8) ? 8 : 0;
    const int no  = (lane & 16) ? 8 : 0;

    // ---- Load Q tile (64 rows) into stage-0 region, extract fragments ----
    {
        const half_t* qp = Qg + gbase + (size_t)q0 * D_;
#pragma unroll
        for (int it = 0; it < 8; ++it) {
            const int ch = tid + it * 64;           // 0..511
            const int r = ch >> 3, c8 = ch & 7;
            cp16(sbase + (r * AST + c8 * 8) * 2, qp + (size_t)r * D_ + c8 * 8);
        }
        CP_COMMIT(); CP_WAIT0();
        __syncthreads();
    }
    uint32_t qf[4][2][4];
#pragma unroll
    for (int ka = 0; ka < 4; ++ka)
#pragma unroll
        for (int m = 0; m < 2; ++m) {
            const uint32_t off =
                (uint32_t)((wq * 32 + m * 16 + l15) * AST + ka * 16 + ao) * 2;
            ldm4(qf[ka][m], sbase + off);
        }
    __syncthreads();

    float O[2][8][4] = {};
    float Ol[2][4] = {};               // l accumulators (ones-column mma)
    const uint32_t ones_b = (lane < 4) ? 0x3C003C00u : 0u;

    auto issue_kv = [&](int s, int t) {    // t = 64-row kv stage (0..31)
        const half_t* srcs[2] = {Kg, Vg};
#pragma unroll
        for (int bi = 0; bi < 2; ++bi) {
            const half_t* g0 = srcs[bi] + gbase + (size_t)(t * 64) * D_;
#pragma unroll
            for (int it = 0; it < 8; ++it) {
                const int ch = tid + it * 64;       // 0..511
                const int r = ch >> 3, c8 = ch & 7;
                cp16(sbase + ((s * 2 + bi) * ABUF64 + r * AST + c8 * 8) * 2,
                     g0 + (size_t)r * D_ + c8 * 8);
            }
        }
        CP_COMMIT();
    };

    issue_kv(0, 0);
    for (int t = 0; t < 32; ++t) {
        CP_WAIT0();
        __syncthreads();
        if (t + 1 < 32) issue_kv((t + 1) & 1, t + 1);
        const uint32_t kTile = sbase + (uint32_t)((t & 1) * 2) * ABUF64 * 2;
        const uint32_t vTile = kTile + ABUF64 * 2;

        // Two independent n-halves (QK n-dim == PV k-dim) bound live S regs.
#pragma unroll
        for (int h = 0; h < 2; ++h) {
            // ---- S = Q K^T for kv rows [h*32, +32) ----
            float S[2][4][4] = {};
#pragma unroll
            for (int ka = 0; ka < 4; ++ka)
#pragma unroll
                for (int s = 0; s < 2; ++s) {
                    const int nb = 2 * h + s;
                    const uint32_t off =
                        (uint32_t)((nb * 16 + l7 + bro) * AST + ka * 16 + bko) * 2;
                    uint32_t kf[4];
                    ldm4(kf, kTile + off);
#pragma unroll
                    for (int m = 0; m < 2; ++m) {
                        mma_f16(S[m][2 * s],     qf[ka][m], kf[0], kf[1]);
                        mma_f16(S[m][2 * s + 1], qf[ka][m], kf[2], kf[3]);
                    }
                }

            // ---- per k-chunk: p = 2^S, then PV ----
#pragma unroll
            for (int s = 0; s < 2; ++s) {
                const int kt = 2 * h + s;
                uint32_t pf[2][4];
#pragma unroll
                for (int m = 0; m < 2; ++m) {
                    pf[m][0] = ex2_h2(pkh(S[m][2 * s][0],     S[m][2 * s][1]));
                    pf[m][1] = ex2_h2(pkh(S[m][2 * s][2],     S[m][2 * s][3]));
                    pf[m][2] = ex2_h2(pkh(S[m][2 * s + 1][0], S[m][2 * s + 1][1]));
                    pf[m][3] = ex2_h2(pkh(S[m][2 * s + 1][2], S[m][2 * s + 1][3]));
                }
#pragma unroll
                for (int nb = 0; nb < 4; ++nb) {
                    const uint32_t off =
                        (uint32_t)((kt * 16 + l15) * AST + nb * 16 + no) * 2;
                    uint32_t vf[4];
                    ldm4t(vf, vTile + off);
#pragma unroll
                    for (int m = 0; m < 2; ++m) {
                        mma_f16(O[m][2 * nb],     pf[m], vf[0], vf[1]);
                        mma_f16(O[m][2 * nb + 1], pf[m], vf[2], vf[3]);
                    }
                }
#pragma unroll
                for (int m = 0; m < 2; ++m)
                    mma_f16(Ol[m], pf[m], ones_b, ones_b);
            }
        }
    }

    // ---- Epilogue: l from ones-column, normalize, store ----
    const int lr = lane >> 2, lc = lane & 3;
#pragma unroll
    for (int m = 0; m < 2; ++m) {
        const float l0 = __shfl_sync(0xffffffffu, Ol[m][0], lane & ~3);
        const float l1 = __shfl_sync(0xffffffffu, Ol[m][2], lane & ~3);
        const float inv0 = 1.f / l0, inv1 = 1.f / l1;
        const size_t rA = (size_t)bb * T_ + q0 + wq * 32 + m * 16 + lr;
        const size_t rB = rA + 8;
#pragma unroll
        for (int jn = 0; jn < 8; ++jn) {
            const int cg = hd * 64 + jn * 8 + lc * 2;
            *(uint32_t*)(Og + rA * D_ + cg) = pkh(O[m][jn][0] * inv0, O[m][jn][1] * inv0);
            *(uint32_t*)(Og + rB * D_ + cg) = pkh(O[m][jn][2] * inv1, O[m][jn][3] * inv1);
        }
    }
}

// ============================================================================
extern "C" void kernel_launch(void* const* d_in, const int* in_sizes, int n_in,
                              void* d_out, int out_size)
{
    (void)in_sizes; (void)n_in; (void)out_size;
    const float* q   = (const float*)d_in[0];
    const float* k   = (const float*)d_in[1];
    const float* v   = (const float*)d_in[2];
    const float* Wq  = (const float*)d_in[3];
    const float* b_q = (const float*)d_in[4];
    const float* Wk  = (const float*)d_in[5];
    const float* b_k = (const float*)d_in[6];
    const float* Wv  = (const float*)d_in[7];
    const float* b_v = (const float*)d_in[8];
    const float* Wo  = (const float*)d_in[9];
    const float* b_o = (const float*)d_in[10];
    float* out = (float*)d_out;

    half_t *in3, *qkv, *att, *w4;
    cudaGetSymbolAddress((void**)&in3, g_in3);
    cudaGetSymbolAddress((void**)&qkv, g_qkv);
    cudaGetSymbolAddress((void**)&att, g_att);
    cudaGetSymbolAddress((void**)&w4,  g_w4);

    cudaFuncSetAttribute(gemm_qkv, cudaFuncAttributeMaxDynamicSharedMemorySize, G_SMEM);
    cudaFuncSetAttribute(gemm_out, cudaFuncAttributeMaxDynamicSharedMemorySize, G_SMEM);
    cudaFuncSetAttribute(attn_f16, cudaFuncAttributeMaxDynamicSharedMemorySize, A_SMEM);

    // Prep
    dim3 tgrid(32, 32, 4), tblk(32, 8);
    transpose_cvt4<<<tgrid, tblk>>>(Wq, Wk, Wv, Wo, w4);
    const int n4 = (int)(MD_ / 4);
    dim3 cgrid(n4 / 256, 3);
    tohalf3<<<cgrid, 256>>>((const float4*)q, (const float4*)k, (const float4*)v,
                            (uint2*)in3, n4);

    // Q/K/V projections (proven R12 config: 128x128 tiles, 256 threads)
    dim3 ggrid(D_ / 128, M_ / 128, 3);   // 8 x 64 x 3
    gemm_qkv<<<ggrid, 256, G_SMEM>>>(in3, w4, b_q, b_k, b_v, qkv);

    // Attention (64 threads/CTA, 2 warps x 32 q-rows, 5 CTAs/SM -> 92.3% wave util)
    dim3 agrid(T_ / 64, H_, B_);         // 32 x 16 x 4 = 2048
    attn_f16<<<agrid, 64, A_SMEM>>>(qkv + 0 * MD_, qkv + 1 * MD_, qkv + 2 * MD_, att);

    // Output projection -> fp32
    dim3 ogrid(D_ / 128, M_ / 128);
    gemm_out<<<ogrid, 256, G_SMEM>>>(att, w4 + 3 * DD_, b_o, out);
}

// round 15
// speedup vs baseline: 1.0250x; 1.0250x over previous
#include <cuda_runtime.h>
#include <cuda_fp16.h>
#include <cstdint>
#include <math.h>

typedef __half half_t;

// Problem constants
#define B_  4
#define T_  2048
#define D_  1024
#define H_  16
#define DH_ 64
#define M_  (B_ * T_)   // 8192
#define DD_ ((size_t)D_ * D_)
#define MD_ ((size_t)M_ * D_)

// Q prescale: 1/sqrt(64) * log2(e)  (softmax done in 2^x domain)
#define QSCALE 0.18033688011110932f

// Scratch
__device__ half_t g_in3[3][MD_];   // q,k,v converted
__device__ half_t g_qkv[3][MD_];   // Q (pre-scaled), K, V
__device__ half_t g_att[MD_];      // attention output
__device__ half_t g_w4[4][DD_];    // Wq,Wk,Wv,Wo transposed [N][K]

// ============================================================================
// PTX helpers
// ============================================================================
__device__ __forceinline__ uint32_t smem_u32(const void* p) {
    uint32_t a;
    asm("{ .reg .u64 t; cvta.to.shared.u64 t, %1; cvt.u32.u64 %0, t; }" : "=r"(a) : "l"(p));
    return a;
}
__device__ __forceinline__ void mma_f16(float* d, const uint32_t* a, uint32_t b0, uint32_t b1) {
    asm volatile(
        "mma.sync.aligned.m16n8k16.row.col.f32.f16.f16.f32 "
        "{%0,%1,%2,%3}, {%4,%5,%6,%7}, {%8,%9}, {%0,%1,%2,%3};"
        : "+f"(d[0]), "+f"(d[1]), "+f"(d[2]), "+f"(d[3])
        : "r"(a[0]), "r"(a[1]), "r"(a[2]), "r"(a[3]), "r"(b0), "r"(b1));
}
__device__ __forceinline__ void ldm4(uint32_t* r, uint32_t a) {
    asm volatile("ldmatrix.sync.aligned.m8n8.x4.shared.b16 {%0,%1,%2,%3}, [%4];"
                 : "=r"(r[0]), "=r"(r[1]), "=r"(r[2]), "=r"(r[3]) : "r"(a));
}
__device__ __forceinline__ void ldm4t(uint32_t* r, uint32_t a) {
    asm volatile("ldmatrix.sync.aligned.m8n8.x4.trans.shared.b16 {%0,%1,%2,%3}, [%4];"
                 : "=r"(r[0]), "=r"(r[1]), "=r"(r[2]), "=r"(r[3]) : "r"(a));
}
__device__ __forceinline__ void cp16(uint32_t dst, const void* src) {
    asm volatile("cp.async.cg.shared.global [%0], [%1], 16;" :: "r"(dst), "l"(src));
}
#define CP_COMMIT() asm volatile("cp.async.commit_group;" ::: "memory")
#define CP_WAIT0()  asm volatile("cp.async.wait_group 0;" ::: "memory")

__device__ __forceinline__ uint32_t pkh(float a, float b) {
    __half2 t = __floats2half2_rn(a, b);
    return *reinterpret_cast<uint32_t*>(&t);
}
__device__ __forceinline__ uint32_t ex2_h2(uint32_t x) {
    uint32_t r;
    asm("ex2.approx.f16x2 %0, %1;" : "=r"(r) : "r"(x));
    return r;
}

// ============================================================================
// transpose + convert all 4 weights (grid.z selects)
// ============================================================================
__global__ __launch_bounds__(256) void transpose_cvt4(
    const float* __restrict__ W0, const float* __restrict__ W1,
    const float* __restrict__ W2, const float* __restrict__ W3,
    half_t* __restrict__ o4)
{
    __shared__ float t[32][33];
    const float* in = (blockIdx.z == 0) ? W0 : (blockIdx.z == 1) ? W1
                     : (blockIdx.z == 2) ? W2 : W3;
    half_t* o = o4 + (size_t)blockIdx.z * DD_;
    int x = blockIdx.x * 32 + threadIdx.x;
    int y0 = blockIdx.y * 32 + threadIdx.y;
#pragma unroll
    for (int i = 0; i < 32; i += 8)
        t[threadIdx.y + i][threadIdx.x] = in[(size_t)(y0 + i) * D_ + x];
    __syncthreads();
    x = blockIdx.y * 32 + threadIdx.x;
    y0 = blockIdx.x * 32 + threadIdx.y;
#pragma unroll
    for (int i = 0; i < 32; i += 8)
        o[(size_t)(y0 + i) * D_ + x] = __float2half_rn(t[threadIdx.x][threadIdx.y + i]);
}

// ============================================================================
// convert q,k,v fp32 -> fp16 in one launch (grid.y selects)
// ============================================================================
__global__ __launch_bounds__(256) void tohalf3(
    const float4* __restrict__ q, const float4* __restrict__ k,
    const float4* __restrict__ v, uint2* __restrict__ out3, int n4)
{
    int i = blockIdx.x * 256 + threadIdx.x;
    if (i >= n4) return;
    const float4* in = (blockIdx.y == 0) ? q : (blockIdx.y == 1) ? k : v;
    uint2* out = out3 + (size_t)blockIdx.y * (MD_ / 4) + i;
    float4 vv = in[i];
    uint2 o;
    o.x = pkh(vv.x, vv.y);
    o.y = pkh(vv.z, vv.w);
    *out = o;
}

// ============================================================================
// fp16 GEMM core: C[128,128 tile] = (A @ Wt^T + bias) * scale
// BK=64, 256 threads (2m x 4n warps), 2-stage cp.async, 1 sync per k-tile.
// (Proven R12 config — at the legacy-HMMA dispatch roofline.)
// ============================================================================
#define GKS 72
#define GTILE (128 * GKS)
#define G_SMEM (2 * 2 * GTILE * 2)   // 73728 bytes

__device__ __forceinline__ void gemm_core(
    const half_t* __restrict__ A, const half_t* __restrict__ Bt,
    const float* __restrict__ bias, float scale,
    float* __restrict__ outF, half_t* __restrict__ outH, half_t* sb)
{
    const uint32_t sbase = smem_u32(sb);
    const int tid = threadIdx.x, lane = tid & 31, wid = tid >> 5;
    const int wm = wid & 1, wn = wid >> 1;
    const int row0 = blockIdx.y * 128, col0 = blockIdx.x * 128;

    float d[4][4][4] = {};

    auto load_stage = [&](int s, int kt) {
        const half_t* srcs[2] = {A, Bt};
        const int rb[2] = {row0, col0};
#pragma unroll
        for (int bi = 0; bi < 2; ++bi) {
#pragma unroll
            for (int it = 0; it < 4; ++it) {
                int ch = tid + it * 256;
                int r = ch >> 3, c8 = ch & 7;
                const half_t* g = srcs[bi] + (size_t)(rb[bi] + r) * D_ + kt * 64 + c8 * 8;
                cp16(sbase + ((s * 2 + bi) * GTILE + r * GKS + c8 * 8) * 2, g);
            }
        }
    };

    auto compute_stage = [&](int s) {
        const uint32_t aB = sbase + (s * 2 + 0) * GTILE * 2;
        const uint32_t bB = sbase + (s * 2 + 1) * GTILE * 2;
        const int l15 = lane & 15, l7 = lane & 7;
        const int aro = (lane & 16) ? 8 : 0;
        const int bko = (lane & 8) ? 8 : 0;
        const int bro = (lane & 16) ? 8 : 0;
#pragma unroll
        for (int kh2 = 0; kh2 < 4; ++kh2) {
            uint32_t af[4][4], bf[2][4];
#pragma unroll
            for (int i = 0; i < 4; ++i) {
                uint32_t off = (uint32_t)((wm * 64 + i * 16 + l15) * GKS + kh2 * 16 + aro) * 2;
                ldm4(af[i], aB + off);
            }
#pragma unroll
            for (int nb = 0; nb < 2; ++nb) {
                uint32_t off = (uint32_t)((wn * 32 + nb * 16 + l7 + bro) * GKS + kh2 * 16 + bko) * 2;
                ldm4(bf[nb], bB + off);
            }
#pragma unroll
            for (int i = 0; i < 4; ++i)
#pragma unroll
                for (int j = 0; j < 4; ++j) {
                    const int nb = j >> 1, hf = (j & 1) * 2;
                    mma_f16(d[i][j], af[i], bf[nb][hf], bf[nb][hf + 1]);
                }
        }
    };

    load_stage(0, 0); CP_COMMIT();
    for (int kt = 0; kt < 16; ++kt) {
        CP_WAIT0();
        __syncthreads();
        if (kt + 1 < 16) { load_stage((kt + 1) & 1, kt + 1); CP_COMMIT(); }
        compute_stage(kt & 1);
    }

    // Epilogue
    const int lr = lane >> 2, lc = lane & 3;
#pragma unroll
    for (int i = 0; i < 4; ++i) {
        const int r0g = row0 + wm * 64 + i * 16 + lr;
#pragma unroll
        for (int j = 0; j < 4; ++j) {
            const int cg = col0 + wn * 32 + j * 8 + lc * 2;
            const float2 bb = *(const float2*)&bias[cg];
            const float v0 = (d[i][j][0] + bb.x) * scale;
            const float v1 = (d[i][j][1] + bb.y) * scale;
            const float v2 = (d[i][j][2] + bb.x) * scale;
            const float v3 = (d[i][j][3] + bb.y) * scale;
            if (outF) {
                *(float2*)&outF[(size_t)r0g * D_ + cg] = make_float2(v0, v1);
                *(float2*)&outF[(size_t)(r0g + 8) * D_ + cg] = make_float2(v2, v3);
            } else {
                *(uint32_t*)(outH + (size_t)r0g * D_ + cg) = pkh(v0, v1);
                *(uint32_t*)(outH + (size_t)(r0g + 8) * D_ + cg) = pkh(v2, v3);
            }
        }
    }
}

__global__ __launch_bounds__(256) void gemm_qkv(
    const half_t* __restrict__ in3, const half_t* __restrict__ w4,
    const float* __restrict__ b_q, const float* __restrict__ b_k,
    const float* __restrict__ b_v, half_t* __restrict__ qkv)
{
    extern __shared__ half_t sb[];
    const int z = blockIdx.z;
    const float* bias = (z == 0) ? b_q : (z == 1) ? b_k : b_v;
    const float scale = (z == 0) ? QSCALE : 1.0f;
    gemm_core(in3 + (size_t)z * MD_, w4 + (size_t)z * DD_, bias, scale,
              nullptr, qkv + (size_t)z * MD_, sb);
}

__global__ __launch_bounds__(256) void gemm_out(
    const half_t* __restrict__ att, const half_t* __restrict__ Wo,
    const float* __restrict__ b_o, float* __restrict__ out)
{
    extern __shared__ half_t sb[];
    gemm_core(att, Wo, b_o, 1.0f, out, nullptr, sb);
}

// ============================================================================
// Flash attention, fp16 mma.sync (f32 acc), static-max log2 softmax.
// R12 config: 32 q-rows per warp (2x K/V frag reuse), per-subtile n-halves,
// 3 CTAs/SM (128 threads). NEW: row-sum l computed on ALU pipe (HADD2 of the
// p fragments + fp32 accumulate + final quad shfl-reduce) instead of the
// ones-column mma — removes 11% of attention HMMA from the tensor pipe.
// KV staged 128 rows, 2-stage cp.async. Q pre-scaled by 0.125*log2(e).
// ============================================================================
#define AST 72
#define SBUFB (128 * AST * 2)
#define A_SMEM (4 * SBUFB)          // 73728 bytes

__global__ __launch_bounds__(128, 3) void attn_f16(
    const half_t* __restrict__ Qg, const half_t* __restrict__ Kg,
    const half_t* __restrict__ Vg, half_t* __restrict__ Og)
{
    extern __shared__ half_t sa_[];
    const uint32_t sbase = smem_u32(sa_);
    const int tid = threadIdx.x, lane = tid & 31, wq = tid >> 5;
    const int q0 = blockIdx.x * 128, hd = blockIdx.y, bb = blockIdx.z;
    const size_t gbase = ((size_t)bb * T_) * D_ + (size_t)hd * 64;

    const int l15 = lane & 15, l7 = lane & 7;
    const int ao  = (lane & 16) ? 8 : 0;
    const int bro = (lane & 16) ? 8 : 0;
    const int bko = (lane & 8) ? 8 : 0;
    const int no  = (lane & 16) ? 8 : 0;

    // ---- Load Q tile (128 rows) into stage-0 region, extract fragments ----
    {
        const half_t* qp = Qg + gbase + (size_t)q0 * D_;
#pragma unroll
        for (int it = 0; it < 8; ++it) {
            const int ch = tid + it * 128;
            const int r = ch >> 3, c8 = ch & 7;
            cp16(sbase + (r * AST + c8 * 8) * 2, qp + (size_t)r * D_ + c8 * 8);
        }
        CP_COMMIT(); CP_WAIT0();
        __syncthreads();
    }
    uint32_t qf[4][2][4];
#pragma unroll
    for (int ka = 0; ka < 4; ++ka)
#pragma unroll
        for (int m = 0; m < 2; ++m) {
            const uint32_t off =
                (uint32_t)((wq * 32 + m * 16 + l15) * AST + ka * 16 + ao) * 2;
            ldm4(qf[ka][m], sbase + off);
        }
    __syncthreads();

    float O[2][8][4] = {};
    float Ol[2][2] = {};               // l partials: [m][row r / row r+8]

    auto issue_kv = [&](int s, int t) {
        const half_t* srcs[2] = {Kg, Vg};
#pragma unroll
        for (int bi = 0; bi < 2; ++bi) {
            const half_t* g0 = srcs[bi] + gbase + (size_t)(t * 128) * D_;
#pragma unroll
            for (int it = 0; it < 8; ++it) {
                const int ch = tid + it * 128;
                const int r = ch >> 3, c8 = ch & 7;
                cp16(sbase + (s * 2 + bi) * SBUFB + (r * AST + c8 * 8) * 2,
                     g0 + (size_t)r * D_ + c8 * 8);
            }
        }
        CP_COMMIT();
    };

    issue_kv(0, 0);
    for (int t = 0; t < 16; ++t) {
        CP_WAIT0();
        __syncthreads();
        if (t + 1 < 16) issue_kv((t + 1) & 1, t + 1);
        const uint32_t kTile = sbase + (uint32_t)((t & 1) * 2) * SBUFB;
        const uint32_t vTile = kTile + SBUFB;

#pragma unroll
        for (int sub = 0; sub < 2; ++sub) {
            const int rofs = sub * 64;
#pragma unroll
            for (int h = 0; h < 2; ++h) {
                // ---- S = Q K^T for kv rows [rofs + h*32, +32) ----
                float S[2][4][4] = {};
#pragma unroll
                for (int ka = 0; ka < 4; ++ka)
#pragma unroll
                    for (int s = 0; s < 2; ++s) {
                        const int nb = 2 * h + s;
                        const uint32_t off =
                            (uint32_t)((rofs + nb * 16 + l7 + bro) * AST + ka * 16 + bko) * 2;
                        uint32_t kf[4];
                        ldm4(kf, kTile + off);
#pragma unroll
                        for (int m = 0; m < 2; ++m) {
                            mma_f16(S[m][2 * s],     qf[ka][m], kf[0], kf[1]);
                            mma_f16(S[m][2 * s + 1], qf[ka][m], kf[2], kf[3]);
                        }
                    }

                // ---- per k-chunk: p = 2^S, PV mma, l on ALU pipe ----
#pragma unroll
                for (int s = 0; s < 2; ++s) {
                    const int kt = 2 * h + s;
                    uint32_t pf[2][4];
#pragma unroll
                    for (int m = 0; m < 2; ++m) {
                        pf[m][0] = ex2_h2(pkh(S[m][2 * s][0],     S[m][2 * s][1]));
                        pf[m][1] = ex2_h2(pkh(S[m][2 * s][2],     S[m][2 * s][3]));
                        pf[m][2] = ex2_h2(pkh(S[m][2 * s + 1][0], S[m][2 * s + 1][1]));
                        pf[m][3] = ex2_h2(pkh(S[m][2 * s + 1][2], S[m][2 * s + 1][3]));
                        // l accumulation: pf[0],pf[2] = row r; pf[1],pf[3] = row r+8
                        const __half2 sr  = __hadd2(*(const __half2*)&pf[m][0],
                                                    *(const __half2*)&pf[m][2]);
                        const __half2 sr8 = __hadd2(*(const __half2*)&pf[m][1],
                                                    *(const __half2*)&pf[m][3]);
                        const float2 fr  = __half22float2(sr);
                        const float2 fr8 = __half22float2(sr8);
                        Ol[m][0] += fr.x + fr.y;
                        Ol[m][1] += fr8.x + fr8.y;
                    }
#pragma unroll
                    for (int nb = 0; nb < 4; ++nb) {
                        const uint32_t off =
                            (uint32_t)((rofs + kt * 16 + l15) * AST + nb * 16 + no) * 2;
                        uint32_t vf[4];
                        ldm4t(vf, vTile + off);
#pragma unroll
                        for (int m = 0; m < 2; ++m) {
                            mma_f16(O[m][2 * nb],     pf[m], vf[0], vf[1]);
                            mma_f16(O[m][2 * nb + 1], pf[m], vf[2], vf[3]);
                        }
                    }
                }
            }
        }
    }

    // ---- Epilogue: quad-reduce l, normalize, store ----
    const int lr = lane >> 2, lc = lane & 3;
#pragma unroll
    for (int m = 0; m < 2; ++m) {
        float l0 = Ol[m][0], l1 = Ol[m][1];
        l0 += __shfl_xor_sync(0xffffffffu, l0, 1);
        l0 += __shfl_xor_sync(0xffffffffu, l0, 2);
        l1 += __shfl_xor_sync(0xffffffffu, l1, 1);
        l1 += __shfl_xor_sync(0xffffffffu, l1, 2);
        const float inv0 = 1.f / l0, inv1 = 1.f / l1;
        const size_t rA = (size_t)bb * T_ + q0 + wq * 32 + m * 16 + lr;
        const size_t rB = rA + 8;
#pragma unroll
        for (int jn = 0; jn < 8; ++jn) {
            const int cg = hd * 64 + jn * 8 + lc * 2;
            *(uint32_t*)(Og + rA * D_ + cg) = pkh(O[m][jn][0] * inv0, O[m][jn][1] * inv0);
            *(uint32_t*)(Og + rB * D_ + cg) = pkh(O[m][jn][2] * inv1, O[m][jn][3] * inv1);
        }
    }
}

// ============================================================================
extern "C" void kernel_launch(void* const* d_in, const int* in_sizes, int n_in,
                              void* d_out, int out_size)
{
    (void)in_sizes; (void)n_in; (void)out_size;
    const float* q   = (const float*)d_in[0];
    const float* k   = (const float*)d_in[1];
    const float* v   = (const float*)d_in[2];
    const float* Wq  = (const float*)d_in[3];
    const float* b_q = (const float*)d_in[4];
    const float* Wk  = (const float*)d_in[5];
    const float* b_k = (const float*)d_in[6];
    const float* Wv  = (const float*)d_in[7];
    const float* b_v = (const float*)d_in[8];
    const float* Wo  = (const float*)d_in[9];
    const float* b_o = (const float*)d_in[10];
    float* out = (float*)d_out;

    half_t *in3, *qkv, *att, *w4;
    cudaGetSymbolAddress((void**)&in3, g_in3);
    cudaGetSymbolAddress((void**)&qkv, g_qkv);
    cudaGetSymbolAddress((void**)&att, g_att);
    cudaGetSymbolAddress((void**)&w4,  g_w4);

    cudaFuncSetAttribute(gemm_qkv, cudaFuncAttributeMaxDynamicSharedMemorySize, G_SMEM);
    cudaFuncSetAttribute(gemm_out, cudaFuncAttributeMaxDynamicSharedMemorySize, G_SMEM);
    cudaFuncSetAttribute(attn_f16, cudaFuncAttributeMaxDynamicSharedMemorySize, A_SMEM);

    // Prep
    dim3 tgrid(32, 32, 4), tblk(32, 8);
    transpose_cvt4<<<tgrid, tblk>>>(Wq, Wk, Wv, Wo, w4);
    const int n4 = (int)(MD_ / 4);
    dim3 cgrid(n4 / 256, 3);
    tohalf3<<<cgrid, 256>>>((const float4*)q, (const float4*)k, (const float4*)v,
                            (uint2*)in3, n4);

    // Q/K/V projections (proven R12 config: 128x128 tiles, 256 threads)
    dim3 ggrid(D_ / 128, M_ / 128, 3);   // 8 x 64 x 3
    gemm_qkv<<<ggrid, 256, G_SMEM>>>(in3, w4, b_q, b_k, b_v, qkv);

    // Attention (128 threads/CTA, 4 warps x 32 q-rows, 3 CTAs/SM)
    dim3 agrid(T_ / 128, H_, B_);
    attn_f16<<<agrid, 128, A_SMEM>>>(qkv + 0 * MD_, qkv + 1 * MD_, qkv + 2 * MD_, att);

    // Output projection -> fp32
    dim3 ogrid(D_ / 128, M_ / 128);
    gemm_out<<<ogrid, 256, G_SMEM>>>(att, w4 + 3 * DD_, b_o, out);
}

// round 16
// speedup vs baseline: 1.0371x; 1.0117x over previous
#include <cuda_runtime.h>
#include <cuda_fp16.h>
#include <cstdint>
#include <math.h>

typedef __half half_t;

// Problem constants
#define B_  4
#define T_  2048
#define D_  1024
#define H_  16
#define DH_ 64
#define M_  (B_ * T_)   // 8192
#define DD_ ((size_t)D_ * D_)
#define MD_ ((size_t)M_ * D_)

// Q prescale: 1/sqrt(64) * log2(e)  (softmax done in 2^x domain)
#define QSCALE 0.18033688011110932f

// Scratch
__device__ half_t g_in3[3][MD_];   // q,k,v converted
__device__ half_t g_qkv[3][MD_];   // Q (pre-scaled), K, V
__device__ half_t g_att[MD_];      // attention output
__device__ half_t g_w4[4][DD_];    // Wq,Wk,Wv,Wo transposed [N][K]

// ============================================================================
// PTX helpers
// ============================================================================
__device__ __forceinline__ uint32_t smem_u32(const void* p) {
    uint32_t a;
    asm("{ .reg .u64 t; cvta.to.shared.u64 t, %1; cvt.u32.u64 %0, t; }" : "=r"(a) : "l"(p));
    return a;
}
__device__ __forceinline__ void mma_f16(float* d, const uint32_t* a, uint32_t b0, uint32_t b1) {
    asm volatile(
        "mma.sync.aligned.m16n8k16.row.col.f32.f16.f16.f32 "
        "{%0,%1,%2,%3}, {%4,%5,%6,%7}, {%8,%9}, {%0,%1,%2,%3};"
        : "+f"(d[0]), "+f"(d[1]), "+f"(d[2]), "+f"(d[3])
        : "r"(a[0]), "r"(a[1]), "r"(a[2]), "r"(a[3]), "r"(b0), "r"(b1));
}
__device__ __forceinline__ void ldm4(uint32_t* r, uint32_t a) {
    asm volatile("ldmatrix.sync.aligned.m8n8.x4.shared.b16 {%0,%1,%2,%3}, [%4];"
                 : "=r"(r[0]), "=r"(r[1]), "=r"(r[2]), "=r"(r[3]) : "r"(a));
}
__device__ __forceinline__ void ldm4t(uint32_t* r, uint32_t a) {
    asm volatile("ldmatrix.sync.aligned.m8n8.x4.trans.shared.b16 {%0,%1,%2,%3}, [%4];"
                 : "=r"(r[0]), "=r"(r[1]), "=r"(r[2]), "=r"(r[3]) : "r"(a));
}
__device__ __forceinline__ void cp16(uint32_t dst, const void* src) {
    asm volatile("cp.async.cg.shared.global [%0], [%1], 16;" :: "r"(dst), "l"(src));
}
#define CP_COMMIT() asm volatile("cp.async.commit_group;" ::: "memory")
#define CP_WAIT0()  asm volatile("cp.async.wait_group 0;" ::: "memory")
#define CP_WAIT1()  asm volatile("cp.async.wait_group 1;" ::: "memory")

__device__ __forceinline__ uint32_t pkh(float a, float b) {
    __half2 t = __floats2half2_rn(a, b);
    return *reinterpret_cast<uint32_t*>(&t);
}
__device__ __forceinline__ uint32_t ex2_h2(uint32_t x) {
    uint32_t r;
    asm("ex2.approx.f16x2 %0, %1;" : "=r"(r) : "r"(x));
    return r;
}

// ============================================================================
// transpose + convert all 4 weights (grid.z selects)
// ============================================================================
__global__ __launch_bounds__(256) void transpose_cvt4(
    const float* __restrict__ W0, const float* __restrict__ W1,
    const float* __restrict__ W2, const float* __restrict__ W3,
    half_t* __restrict__ o4)
{
    __shared__ float t[32][33];
    const float* in = (blockIdx.z == 0) ? W0 : (blockIdx.z == 1) ? W1
                     : (blockIdx.z == 2) ? W2 : W3;
    half_t* o = o4 + (size_t)blockIdx.z * DD_;
    int x = blockIdx.x * 32 + threadIdx.x;
    int y0 = blockIdx.y * 32 + threadIdx.y;
#pragma unroll
    for (int i = 0; i < 32; i += 8)
        t[threadIdx.y + i][threadIdx.x] = in[(size_t)(y0 + i) * D_ + x];
    __syncthreads();
    x = blockIdx.y * 32 + threadIdx.x;
    y0 = blockIdx.x * 32 + threadIdx.y;
#pragma unroll
    for (int i = 0; i < 32; i += 8)
        o[(size_t)(y0 + i) * D_ + x] = __float2half_rn(t[threadIdx.x][threadIdx.y + i]);
}

// ============================================================================
// convert q,k,v fp32 -> fp16 in one launch (grid.y selects)
// ============================================================================
__global__ __launch_bounds__(256) void tohalf3(
    const float4* __restrict__ q, const float4* __restrict__ k,
    const float4* __restrict__ v, uint2* __restrict__ out3, int n4)
{
    int i = blockIdx.x * 256 + threadIdx.x;
    if (i >= n4) return;
    const float4* in = (blockIdx.y == 0) ? q : (blockIdx.y == 1) ? k : v;
    uint2* out = out3 + (size_t)blockIdx.y * (MD_ / 4) + i;
    float4 vv = in[i];
    uint2 o;
    o.x = pkh(vv.x, vv.y);
    o.y = pkh(vv.z, vv.w);
    *out = o;
}

// ============================================================================
// fp16 GEMM core: C[128,128 tile] = (A @ Wt^T + bias) * scale
// BK=64, 256 threads (2m x 4n warps). 3-STAGE cp.async pipeline
// (wait_group 1 + always-commit): every tile load gets two full compute
// phases of latency cover — fixes the ~50% tensor idle of the 2-stage loop.
// 2 CTAs/SM (2 x 110.6KB smem = 221KB <= 228KB).
// ============================================================================
#define GKS 72
#define GTILE (128 * GKS)
#define G_SMEM (3 * 2 * GTILE * 2)   // 110592 bytes (3 stages x (A,B))

__device__ __forceinline__ void gemm_core(
    const half_t* __restrict__ A, const half_t* __restrict__ Bt,
    const float* __restrict__ bias, float scale,
    float* __restrict__ outF, half_t* __restrict__ outH, half_t* sb)
{
    const uint32_t sbase = smem_u32(sb);
    const int tid = threadIdx.x, lane = tid & 31, wid = tid >> 5;
    const int wm = wid & 1, wn = wid >> 1;
    const int row0 = blockIdx.y * 128, col0 = blockIdx.x * 128;

    float d[4][4][4] = {};

    auto load_stage = [&](int s, int kt) {
        const half_t* srcs[2] = {A, Bt};
        const int rb[2] = {row0, col0};
#pragma unroll
        for (int bi = 0; bi < 2; ++bi) {
#pragma unroll
            for (int it = 0; it < 4; ++it) {
                int ch = tid + it * 256;
                int r = ch >> 3, c8 = ch & 7;
                const half_t* g = srcs[bi] + (size_t)(rb[bi] + r) * D_ + kt * 64 + c8 * 8;
                cp16(sbase + ((s * 2 + bi) * GTILE + r * GKS + c8 * 8) * 2, g);
            }
        }
    };

    auto compute_stage = [&](int s) {
        const uint32_t aB = sbase + (s * 2 + 0) * GTILE * 2;
        const uint32_t bB = sbase + (s * 2 + 1) * GTILE * 2;
        const int l15 = lane & 15, l7 = lane & 7;
        const int aro = (lane & 16) ? 8 : 0;
        const int bko = (lane & 8) ? 8 : 0;
        const int bro = (lane & 16) ? 8 : 0;
#pragma unroll
        for (int kh2 = 0; kh2 < 4; ++kh2) {
            uint32_t af[4][4], bf[2][4];
#pragma unroll
            for (int i = 0; i < 4; ++i) {
                uint32_t off = (uint32_t)((wm * 64 + i * 16 + l15) * GKS + kh2 * 16 + aro) * 2;
                ldm4(af[i], aB + off);
            }
#pragma unroll
            for (int nb = 0; nb < 2; ++nb) {
                uint32_t off = (uint32_t)((wn * 32 + nb * 16 + l7 + bro) * GKS + kh2 * 16 + bko) * 2;
                ldm4(bf[nb], bB + off);
            }
#pragma unroll
            for (int i = 0; i < 4; ++i)
#pragma unroll
                for (int j = 0; j < 4; ++j) {
                    const int nb = j >> 1, hf = (j & 1) * 2;
                    mma_f16(d[i][j], af[i], bf[nb][hf], bf[nb][hf + 1]);
                }
        }
    };

    // 3-stage pipeline: prologue fills stages 0,1; each iter waits for the
    // oldest group, then issues kt+2 (or an empty group) and computes kt.
    load_stage(0, 0); CP_COMMIT();
    load_stage(1, 1); CP_COMMIT();
#pragma unroll 1
    for (int kt = 0; kt < 16; ++kt) {
        CP_WAIT1();                  // group kt landed (kt+1 may be in flight)
        __syncthreads();             // all warps done reading stage (kt+2)%3
        if (kt + 2 < 16) load_stage((kt + 2) % 3, kt + 2);
        CP_COMMIT();                 // always commit (empty group near the tail)
        compute_stage(kt % 3);
    }

    // Epilogue
    const int lr = lane >> 2, lc = lane & 3;
#pragma unroll
    for (int i = 0; i < 4; ++i) {
        const int r0g = row0 + wm * 64 + i * 16 + lr;
#pragma unroll
        for (int j = 0; j < 4; ++j) {
            const int cg = col0 + wn * 32 + j * 8 + lc * 2;
            const float2 bb = *(const float2*)&bias[cg];
            const float v0 = (d[i][j][0] + bb.x) * scale;
            const float v1 = (d[i][j][1] + bb.y) * scale;
            const float v2 = (d[i][j][2] + bb.x) * scale;
            const float v3 = (d[i][j][3] + bb.y) * scale;
            if (outF) {
                *(float2*)&outF[(size_t)r0g * D_ + cg] = make_float2(v0, v1);
                *(float2*)&outF[(size_t)(r0g + 8) * D_ + cg] = make_float2(v2, v3);
            } else {
                *(uint32_t*)(outH + (size_t)r0g * D_ + cg) = pkh(v0, v1);
                *(uint32_t*)(outH + (size_t)(r0g + 8) * D_ + cg) = pkh(v2, v3);
            }
        }
    }
}

__global__ __launch_bounds__(256) void gemm_qkv(
    const half_t* __restrict__ in3, const half_t* __restrict__ w4,
    const float* __restrict__ b_q, const float* __restrict__ b_k,
    const float* __restrict__ b_v, half_t* __restrict__ qkv)
{
    extern __shared__ half_t sb[];
    const int z = blockIdx.z;
    const float* bias = (z == 0) ? b_q : (z == 1) ? b_k : b_v;
    const float scale = (z == 0) ? QSCALE : 1.0f;
    gemm_core(in3 + (size_t)z * MD_, w4 + (size_t)z * DD_, bias, scale,
              nullptr, qkv + (size_t)z * MD_, sb);
}

__global__ __launch_bounds__(256) void gemm_out(
    const half_t* __restrict__ att, const half_t* __restrict__ Wo,
    const float* __restrict__ b_o, float* __restrict__ out)
{
    extern __shared__ half_t sb[];
    gemm_core(att, Wo, b_o, 1.0f, out, nullptr, sb);
}

// ============================================================================
// Flash attention — EXACT R12 winner config (proven 161us / tensor 75%):
// fp16 mma.sync (f32 acc), static-max log2 softmax, 32 q-rows per warp,
// per-subtile n-halves, ones-column mma for l, 3 CTAs/SM, 128 threads,
// KV staged 128 rows, 2-stage cp.async. Q pre-scaled by 0.125*log2(e).
// ============================================================================
#define AST 72
#define SBUFB (128 * AST * 2)
#define A_SMEM (4 * SBUFB)          // 73728 bytes

__global__ __launch_bounds__(128, 3) void attn_f16(
    const half_t* __restrict__ Qg, const half_t* __restrict__ Kg,
    const half_t* __restrict__ Vg, half_t* __restrict__ Og)
{
    extern __shared__ half_t sa_[];
    const uint32_t sbase = smem_u32(sa_);
    const int tid = threadIdx.x, lane = tid & 31, wq = tid >> 5;
    const int q0 = blockIdx.x * 128, hd = blockIdx.y, bb = blockIdx.z;
    const size_t gbase = ((size_t)bb * T_) * D_ + (size_t)hd * 64;

    const int l15 = lane & 15, l7 = lane & 7;
    const int ao  = (lane & 16) ? 8 : 0;
    const int bro = (lane & 16) ? 8 : 0;
    const int bko = (lane & 8) ? 8 : 0;
    const int no  = (lane & 16) ? 8 : 0;

    // ---- Load Q tile (128 rows) into stage-0 region, extract fragments ----
    {
        const half_t* qp = Qg + gbase + (size_t)q0 * D_;
#pragma unroll
        for (int it = 0; it < 8; ++it) {
            const int ch = tid + it * 128;
            const int r = ch >> 3, c8 = ch & 7;
            cp16(sbase + (r * AST + c8 * 8) * 2, qp + (size_t)r * D_ + c8 * 8);
        }
        CP_COMMIT(); CP_WAIT0();
        __syncthreads();
    }
    uint32_t qf[4][2][4];
#pragma unroll
    for (int ka = 0; ka < 4; ++ka)
#pragma unroll
        for (int m = 0; m < 2; ++m) {
            const uint32_t off =
                (uint32_t)((wq * 32 + m * 16 + l15) * AST + ka * 16 + ao) * 2;
            ldm4(qf[ka][m], sbase + off);
        }
    __syncthreads();

    float O[2][8][4] = {};
    float Ol[2][4] = {};               // l accumulators (ones-column mma)
    const uint32_t ones_b = (lane < 4) ? 0x3C003C00u : 0u;

    auto issue_kv = [&](int s, int t) {
        const half_t* srcs[2] = {Kg, Vg};
#pragma unroll
        for (int bi = 0; bi < 2; ++bi) {
            const half_t* g0 = srcs[bi] + gbase + (size_t)(t * 128) * D_;
#pragma unroll
            for (int it = 0; it < 8; ++it) {
                const int ch = tid + it * 128;
                const int r = ch >> 3, c8 = ch & 7;
                cp16(sbase + (s * 2 + bi) * SBUFB + (r * AST + c8 * 8) * 2,
                     g0 + (size_t)r * D_ + c8 * 8);
            }
        }
        CP_COMMIT();
    };

    issue_kv(0, 0);
    for (int t = 0; t < 16; ++t) {
        CP_WAIT0();
        __syncthreads();
        if (t + 1 < 16) issue_kv((t + 1) & 1, t + 1);
        const uint32_t kTile = sbase + (uint32_t)((t & 1) * 2) * SBUFB;
        const uint32_t vTile = kTile + SBUFB;

#pragma unroll
        for (int sub = 0; sub < 2; ++sub) {
            const int rofs = sub * 64;
#pragma unroll
            for (int h = 0; h < 2; ++h) {
                // ---- S = Q K^T for kv rows [rofs + h*32, +32) ----
                float S[2][4][4] = {};
#pragma unroll
                for (int ka = 0; ka < 4; ++ka)
#pragma unroll
                    for (int s = 0; s < 2; ++s) {
                        const int nb = 2 * h + s;
                        const uint32_t off =
                            (uint32_t)((rofs + nb * 16 + l7 + bro) * AST + ka * 16 + bko) * 2;
                        uint32_t kf[4];
                        ldm4(kf, kTile + off);
#pragma unroll
                        for (int m = 0; m < 2; ++m) {
                            mma_f16(S[m][2 * s],     qf[ka][m], kf[0], kf[1]);
                            mma_f16(S[m][2 * s + 1], qf[ka][m], kf[2], kf[3]);
                        }
                    }

                // ---- per k-chunk: p = 2^S, then PV ----
#pragma unroll
                for (int s = 0; s < 2; ++s) {
                    const int kt = 2 * h + s;
                    uint32_t pf[2][4];
#pragma unroll
                    for (int m = 0; m < 2; ++m) {
                        pf[m][0] = ex2_h2(pkh(S[m][2 * s][0],     S[m][2 * s][1]));
                        pf[m][1] = ex2_h2(pkh(S[m][2 * s][2],     S[m][2 * s][3]));
                        pf[m][2] = ex2_h2(pkh(S[m][2 * s + 1][0], S[m][2 * s + 1][1]));
                        pf[m][3] = ex2_h2(pkh(S[m][2 * s + 1][2], S[m][2 * s + 1][3]));
                    }
#pragma unroll
                    for (int nb = 0; nb < 4; ++nb) {
                        const uint32_t off =
                            (uint32_t)((rofs + kt * 16 + l15) * AST + nb * 16 + no) * 2;
                        uint32_t vf[4];
                        ldm4t(vf, vTile + off);
#pragma unroll
                        for (int m = 0; m < 2; ++m) {
                            mma_f16(O[m][2 * nb],     pf[m], vf[0], vf[1]);
                            mma_f16(O[m][2 * nb + 1], pf[m], vf[2], vf[3]);
                        }
                    }
#pragma unroll
                    for (int m = 0; m < 2; ++m)
                        mma_f16(Ol[m], pf[m], ones_b, ones_b);
                }
            }
        }
    }

    // ---- Epilogue: l from ones-column, normalize, store ----
    const int lr = lane >> 2, lc = lane & 3;
#pragma unroll
    for (int m = 0; m < 2; ++m) {
        const float l0 = __shfl_sync(0xffffffffu, Ol[m][0], lane & ~3);
        const float l1 = __shfl_sync(0xffffffffu, Ol[m][2], lane & ~3);
        const float inv0 = 1.f / l0, inv1 = 1.f / l1;
        const size_t rA = (size_t)bb * T_ + q0 + wq * 32 + m * 16 + lr;
        const size_t rB = rA + 8;
#pragma unroll
        for (int jn = 0; jn < 8; ++jn) {
            const int cg = hd * 64 + jn * 8 + lc * 2;
            *(uint32_t*)(Og + rA * D_ + cg) = pkh(O[m][jn][0] * inv0, O[m][jn][1] * inv0);
            *(uint32_t*)(Og + rB * D_ + cg) = pkh(O[m][jn][2] * inv1, O[m][jn][3] * inv1);
        }
    }
}

// ============================================================================
extern "C" void kernel_launch(void* const* d_in, const int* in_sizes, int n_in,
                              void* d_out, int out_size)
{
    (void)in_sizes; (void)n_in; (void)out_size;
    const float* q   = (const float*)d_in[0];
    const float* k   = (const float*)d_in[1];
    const float* v   = (const float*)d_in[2];
    const float* Wq  = (const float*)d_in[3];
    const float* b_q = (const float*)d_in[4];
    const float* Wk  = (const float*)d_in[5];
    const float* b_k = (const float*)d_in[6];
    const float* Wv  = (const float*)d_in[7];
    const float* b_v = (const float*)d_in[8];
    const float* Wo  = (const float*)d_in[9];
    const float* b_o = (const float*)d_in[10];
    float* out = (float*)d_out;

    half_t *in3, *qkv, *att, *w4;
    cudaGetSymbolAddress((void**)&in3, g_in3);
    cudaGetSymbolAddress((void**)&qkv, g_qkv);
    cudaGetSymbolAddress((void**)&att, g_att);
    cudaGetSymbolAddress((void**)&w4,  g_w4);

    cudaFuncSetAttribute(gemm_qkv, cudaFuncAttributeMaxDynamicSharedMemorySize, G_SMEM);
    cudaFuncSetAttribute(gemm_out, cudaFuncAttributeMaxDynamicSharedMemorySize, G_SMEM);
    cudaFuncSetAttribute(attn_f16, cudaFuncAttributeMaxDynamicSharedMemorySize, A_SMEM);

    // Prep
    dim3 tgrid(32, 32, 4), tblk(32, 8);
    transpose_cvt4<<<tgrid, tblk>>>(Wq, Wk, Wv, Wo, w4);
    const int n4 = (int)(MD_ / 4);
    dim3 cgrid(n4 / 256, 3);
    tohalf3<<<cgrid, 256>>>((const float4*)q, (const float4*)k, (const float4*)v,
                            (uint2*)in3, n4);

    // Q/K/V projections (128x128 tiles, 256 threads, 3-stage pipeline)
    dim3 ggrid(D_ / 128, M_ / 128, 3);   // 8 x 64 x 3
    gemm_qkv<<<ggrid, 256, G_SMEM>>>(in3, w4, b_q, b_k, b_v, qkv);

    // Attention (R12 winner: 128 threads/CTA, 4 warps x 32 q-rows, 3 CTAs/SM)
    dim3 agrid(T_ / 128, H_, B_);
    attn_f16<<<agrid, 128, A_SMEM>>>(qkv + 0 * MD_, qkv + 1 * MD_, qkv + 2 * MD_, att);

    // Output projection -> fp32 (3-stage pipeline)
    dim3 ogrid(D_ / 128, M_ / 128);
    gemm_out<<<ogrid, 256, G_SMEM>>>(att, w4 + 3 * DD_, b_o, out);
}

// round 17
// speedup vs baseline: 1.0828x; 1.0441x over previous
#include <cuda_runtime.h>
#include <cuda_fp16.h>
#include <cstdint>
#include <math.h>

typedef __half half_t;

// Problem constants
#define B_  4
#define T_  2048
#define D_  1024
#define H_  16
#define DH_ 64
#define M_  (B_ * T_)   // 8192
#define DD_ ((size_t)D_ * D_)
#define MD_ ((size_t)M_ * D_)

// Q prescale: 1/sqrt(64) * log2(e)  (softmax done in 2^x domain)
#define QSCALE 0.18033688011110932f

// Scratch
__device__ half_t g_in3[3][MD_];   // q,k,v converted
__device__ half_t g_qkv[3][MD_];   // Q (pre-scaled), K, V
__device__ half_t g_att[MD_];      // attention output
__device__ half_t g_w4[4][DD_];    // Wq,Wk,Wv,Wo transposed [N][K]

// ============================================================================
// PTX helpers
// ============================================================================
__device__ __forceinline__ uint32_t smem_u32(const void* p) {
    uint32_t a;
    asm("{ .reg .u64 t; cvta.to.shared.u64 t, %1; cvt.u32.u64 %0, t; }" : "=r"(a) : "l"(p));
    return a;
}
__device__ __forceinline__ void mma_f16(float* d, const uint32_t* a, uint32_t b0, uint32_t b1) {
    asm volatile(
        "mma.sync.aligned.m16n8k16.row.col.f32.f16.f16.f32 "
        "{%0,%1,%2,%3}, {%4,%5,%6,%7}, {%8,%9}, {%0,%1,%2,%3};"
        : "+f"(d[0]), "+f"(d[1]), "+f"(d[2]), "+f"(d[3])
        : "r"(a[0]), "r"(a[1]), "r"(a[2]), "r"(a[3]), "r"(b0), "r"(b1));
}
__device__ __forceinline__ void ldm4(uint32_t* r, uint32_t a) {
    asm volatile("ldmatrix.sync.aligned.m8n8.x4.shared.b16 {%0,%1,%2,%3}, [%4];"
                 : "=r"(r[0]), "=r"(r[1]), "=r"(r[2]), "=r"(r[3]) : "r"(a));
}
__device__ __forceinline__ void ldm4t(uint32_t* r, uint32_t a) {
    asm volatile("ldmatrix.sync.aligned.m8n8.x4.trans.shared.b16 {%0,%1,%2,%3}, [%4];"
                 : "=r"(r[0]), "=r"(r[1]), "=r"(r[2]), "=r"(r[3]) : "r"(a));
}
__device__ __forceinline__ void cp16(uint32_t dst, const void* src) {
    asm volatile("cp.async.cg.shared.global [%0], [%1], 16;" :: "r"(dst), "l"(src));
}
#define CP_COMMIT() asm volatile("cp.async.commit_group;" ::: "memory")
#define CP_WAIT0()  asm volatile("cp.async.wait_group 0;" ::: "memory")

__device__ __forceinline__ uint32_t pkh(float a, float b) {
    __half2 t = __floats2half2_rn(a, b);
    return *reinterpret_cast<uint32_t*>(&t);
}
__device__ __forceinline__ uint32_t ex2_h2(uint32_t x) {
    uint32_t r;
    asm("ex2.approx.f16x2 %0, %1;" : "=r"(r) : "r"(x));
    return r;
}

// ============================================================================
// transpose + convert all 4 weights (grid.z selects)
// ============================================================================
__global__ __launch_bounds__(256) void transpose_cvt4(
    const float* __restrict__ W0, const float* __restrict__ W1,
    const float* __restrict__ W2, const float* __restrict__ W3,
    half_t* __restrict__ o4)
{
    __shared__ float t[32][33];
    const float* in = (blockIdx.z == 0) ? W0 : (blockIdx.z == 1) ? W1
                     : (blockIdx.z == 2) ? W2 : W3;
    half_t* o = o4 + (size_t)blockIdx.z * DD_;
    int x = blockIdx.x * 32 + threadIdx.x;
    int y0 = blockIdx.y * 32 + threadIdx.y;
#pragma unroll
    for (int i = 0; i < 32; i += 8)
        t[threadIdx.y + i][threadIdx.x] = in[(size_t)(y0 + i) * D_ + x];
    __syncthreads();
    x = blockIdx.y * 32 + threadIdx.x;
    y0 = blockIdx.x * 32 + threadIdx.y;
#pragma unroll
    for (int i = 0; i < 32; i += 8)
        o[(size_t)(y0 + i) * D_ + x] = __float2half_rn(t[threadIdx.x][threadIdx.y + i]);
}

// ============================================================================
// convert q,k,v fp32 -> fp16 in one launch (grid.y selects)
// ============================================================================
__global__ __launch_bounds__(256) void tohalf3(
    const float4* __restrict__ q, const float4* __restrict__ k,
    const float4* __restrict__ v, uint2* __restrict__ out3, int n4)
{
    int i = blockIdx.x * 256 + threadIdx.x;
    if (i >= n4) return;
    const float4* in = (blockIdx.y == 0) ? q : (blockIdx.y == 1) ? k : v;
    uint2* out = out3 + (size_t)blockIdx.y * (MD_ / 4) + i;
    float4 vv = in[i];
    uint2 o;
    o.x = pkh(vv.x, vv.y);
    o.y = pkh(vv.z, vv.w);
    *out = o;
}

// ============================================================================
// QKV GEMM: tile 128x128, BK=64, 128 threads = 4 warps (2m x 2n),
// WARP TILE 64x64 -> LDSM/HMMA ratio 0.25 (was 0.375) — the same fragment-
// reuse fix that worked for attention (R11). B loaded in n32 halves to keep
// live regs ~164 <= 168 cap. 3 CTAs/SM, 2-stage cp.async, 1 sync/k-tile.
// ============================================================================
#define QKS 72
#define QTILE (128 * QKS)
#define Q_SMEM (2 * 2 * QTILE * 2)   // 73728 bytes

__global__ __launch_bounds__(128, 3) void gemm_qkv(
    const half_t* __restrict__ in3, const half_t* __restrict__ w4,
    const float* __restrict__ b_q, const float* __restrict__ b_k,
    const float* __restrict__ b_v, half_t* __restrict__ qkv)
{
    extern __shared__ half_t sb[];
    const uint32_t sbase = smem_u32(sb);
    const int tid = threadIdx.x, lane = tid & 31, wid = tid >> 5;
    const int wm = wid & 1, wn = wid >> 1;          // 2m x 2n warps
    const int row0 = blockIdx.y * 128, col0 = blockIdx.x * 128;
    const int z = blockIdx.z;
    const half_t* A  = in3 + (size_t)z * MD_;
    const half_t* Bt = w4 + (size_t)z * DD_;
    const float* bias = (z == 0) ? b_q : (z == 1) ? b_k : b_v;
    const float scale = (z == 0) ? QSCALE : 1.0f;

    const int l15 = lane & 15, l7 = lane & 7;
    const int aro = (lane & 16) ? 8 : 0;
    const int bko = (lane & 8) ? 8 : 0;
    const int bro = (lane & 16) ? 8 : 0;

    float d[4][8][4] = {};   // 4 m-frags x 8 n8-blocks

    auto load_stage = [&](int s, int kt) {
        const half_t* srcs[2] = {A, Bt};
        const int rb[2] = {row0, col0};
#pragma unroll
        for (int bi = 0; bi < 2; ++bi) {
#pragma unroll
            for (int it = 0; it < 8; ++it) {
                int ch = tid + it * 128;             // 0..1023
                int r = ch >> 3, c8 = ch & 7;
                const half_t* g = srcs[bi] + (size_t)(rb[bi] + r) * D_ + kt * 64 + c8 * 8;
                cp16(sbase + ((s * 2 + bi) * QTILE + r * QKS + c8 * 8) * 2, g);
            }
        }
    };

    auto compute_stage = [&](int s) {
        const uint32_t aB = sbase + (s * 2 + 0) * QTILE * 2;
        const uint32_t bB = sbase + (s * 2 + 1) * QTILE * 2;
#pragma unroll
        for (int kh2 = 0; kh2 < 4; ++kh2) {
            uint32_t af[4][4];
#pragma unroll
            for (int i = 0; i < 4; ++i) {
                uint32_t off = (uint32_t)((wm * 64 + i * 16 + l15) * QKS + kh2 * 16 + aro) * 2;
                ldm4(af[i], aB + off);
            }
            // B in two n32 halves: A fragments reused across both (ratio 0.25)
#pragma unroll
            for (int nh = 0; nh < 2; ++nh) {
                uint32_t bf[2][4];
#pragma unroll
                for (int s2 = 0; s2 < 2; ++s2) {
                    uint32_t off = (uint32_t)((wn * 64 + nh * 32 + s2 * 16 + l7 + bro) * QKS
                                              + kh2 * 16 + bko) * 2;
                    ldm4(bf[s2], bB + off);
                }
#pragma unroll
                for (int i = 0; i < 4; ++i)
#pragma unroll
                    for (int j = 0; j < 4; ++j) {
                        const int nb = j >> 1, hf = (j & 1) * 2;
                        mma_f16(d[i][nh * 4 + j], af[i], bf[nb][hf], bf[nb][hf + 1]);
                    }
            }
        }
    };

    load_stage(0, 0); CP_COMMIT();
    for (int kt = 0; kt < 16; ++kt) {
        CP_WAIT0();
        __syncthreads();
        if (kt + 1 < 16) { load_stage((kt + 1) & 1, kt + 1); CP_COMMIT(); }
        compute_stage(kt & 1);
    }

    // Epilogue: each warp writes its 64x64 block
    const int lr = lane >> 2, lc = lane & 3;
    half_t* outH = qkv + (size_t)z * MD_;
#pragma unroll
    for (int i = 0; i < 4; ++i) {
        const int r0g = row0 + wm * 64 + i * 16 + lr;
#pragma unroll
        for (int j = 0; j < 8; ++j) {
            const int cg = col0 + wn * 64 + j * 8 + lc * 2;
            const float2 bb = *(const float2*)&bias[cg];
            const float v0 = (d[i][j][0] + bb.x) * scale;
            const float v1 = (d[i][j][1] + bb.y) * scale;
            const float v2 = (d[i][j][2] + bb.x) * scale;
            const float v3 = (d[i][j][3] + bb.y) * scale;
            *(uint32_t*)(outH + (size_t)r0g * D_ + cg) = pkh(v0, v1);
            *(uint32_t*)(outH + (size_t)(r0g + 8) * D_ + cg) = pkh(v2, v3);
        }
    }
}

// ============================================================================
// Output GEMM: proven R12 config — tile 128x128, BK=64, 256 threads
// (2m x 4n warps), 2-stage cp.async. (Wave util 86.5% at this grid; the
// 128-thread shape would quantize worse here.)
// ============================================================================
#define GKS 72
#define GTILE (128 * GKS)
#define G_SMEM (2 * 2 * GTILE * 2)   // 73728 bytes

__global__ __launch_bounds__(256) void gemm_out(
    const half_t* __restrict__ A, const half_t* __restrict__ Bt,
    const float* __restrict__ bias, float* __restrict__ outF)
{
    extern __shared__ half_t sb[];
    const uint32_t sbase = smem_u32(sb);
    const int tid = threadIdx.x, lane = tid & 31, wid = tid >> 5;
    const int wm = wid & 1, wn = wid >> 1;
    const int row0 = blockIdx.y * 128, col0 = blockIdx.x * 128;

    float d[4][4][4] = {};

    auto load_stage = [&](int s, int kt) {
        const half_t* srcs[2] = {A, Bt};
        const int rb[2] = {row0, col0};
#pragma unroll
        for (int bi = 0; bi < 2; ++bi) {
#pragma unroll
            for (int it = 0; it < 4; ++it) {
                int ch = tid + it * 256;
                int r = ch >> 3, c8 = ch & 7;
                const half_t* g = srcs[bi] + (size_t)(rb[bi] + r) * D_ + kt * 64 + c8 * 8;
                cp16(sbase + ((s * 2 + bi) * GTILE + r * GKS + c8 * 8) * 2, g);
            }
        }
    };

    auto compute_stage = [&](int s) {
        const uint32_t aB = sbase + (s * 2 + 0) * GTILE * 2;
        const uint32_t bB = sbase + (s * 2 + 1) * GTILE * 2;
        const int l15 = lane & 15, l7 = lane & 7;
        const int aro = (lane & 16) ? 8 : 0;
        const int bko = (lane & 8) ? 8 : 0;
        const int bro = (lane & 16) ? 8 : 0;
#pragma unroll
        for (int kh2 = 0; kh2 < 4; ++kh2) {
            uint32_t af[4][4], bf[2][4];
#pragma unroll
            for (int i = 0; i < 4; ++i) {
                uint32_t off = (uint32_t)((wm * 64 + i * 16 + l15) * GKS + kh2 * 16 + aro) * 2;
                ldm4(af[i], aB + off);
            }
#pragma unroll
            for (int nb = 0; nb < 2; ++nb) {
                uint32_t off = (uint32_t)((wn * 32 + nb * 16 + l7 + bro) * GKS + kh2 * 16 + bko) * 2;
                ldm4(bf[nb], bB + off);
            }
#pragma unroll
            for (int i = 0; i < 4; ++i)
#pragma unroll
                for (int j = 0; j < 4; ++j) {
                    const int nb = j >> 1, hf = (j & 1) * 2;
                    mma_f16(d[i][j], af[i], bf[nb][hf], bf[nb][hf + 1]);
                }
        }
    };

    load_stage(0, 0); CP_COMMIT();
    for (int kt = 0; kt < 16; ++kt) {
        CP_WAIT0();
        __syncthreads();
        if (kt + 1 < 16) { load_stage((kt + 1) & 1, kt + 1); CP_COMMIT(); }
        compute_stage(kt & 1);
    }

    const int lr = lane >> 2, lc = lane & 3;
#pragma unroll
    for (int i = 0; i < 4; ++i) {
        const int r0g = row0 + wm * 64 + i * 16 + lr;
#pragma unroll
        for (int j = 0; j < 4; ++j) {
            const int cg = col0 + wn * 32 + j * 8 + lc * 2;
            const float2 bb = *(const float2*)&bias[cg];
            *(float2*)&outF[(size_t)r0g * D_ + cg] =
                make_float2(d[i][j][0] + bb.x, d[i][j][1] + bb.y);
            *(float2*)&outF[(size_t)(r0g + 8) * D_ + cg] =
                make_float2(d[i][j][2] + bb.x, d[i][j][3] + bb.y);
        }
    }
}

// ============================================================================
// Flash attention — EXACT R12 winner config (161us / tensor 75%):
// fp16 mma.sync (f32 acc), static-max log2 softmax, 32 q-rows per warp,
// per-subtile n-halves, ones-column mma for l, 3 CTAs/SM, 128 threads,
// KV staged 128 rows, 2-stage cp.async. Q pre-scaled by 0.125*log2(e).
// ============================================================================
#define AST 72
#define SBUFB (128 * AST * 2)
#define A_SMEM (4 * SBUFB)          // 73728 bytes

__global__ __launch_bounds__(128, 3) void attn_f16(
    const half_t* __restrict__ Qg, const half_t* __restrict__ Kg,
    const half_t* __restrict__ Vg, half_t* __restrict__ Og)
{
    extern __shared__ half_t sa_[];
    const uint32_t sbase = smem_u32(sa_);
    const int tid = threadIdx.x, lane = tid & 31, wq = tid >> 5;
    const int q0 = blockIdx.x * 128, hd = blockIdx.y, bb = blockIdx.z;
    const size_t gbase = ((size_t)bb * T_) * D_ + (size_t)hd * 64;

    const int l15 = lane & 15, l7 = lane & 7;
    const int ao  = (lane & 16) ? 8 : 0;
    const int bro = (lane & 16) ? 8 : 0;
    const int bko = (lane & 8) ? 8 : 0;
    const int no  = (lane & 16) ? 8 : 0;

    // ---- Load Q tile (128 rows) into stage-0 region, extract fragments ----
    {
        const half_t* qp = Qg + gbase + (size_t)q0 * D_;
#pragma unroll
        for (int it = 0; it < 8; ++it) {
            const int ch = tid + it * 128;
            const int r = ch >> 3, c8 = ch & 7;
            cp16(sbase + (r * AST + c8 * 8) * 2, qp + (size_t)r * D_ + c8 * 8);
        }
        CP_COMMIT(); CP_WAIT0();
        __syncthreads();
    }
    uint32_t qf[4][2][4];
#pragma unroll
    for (int ka = 0; ka < 4; ++ka)
#pragma unroll
        for (int m = 0; m < 2; ++m) {
            const uint32_t off =
                (uint32_t)((wq * 32 + m * 16 + l15) * AST + ka * 16 + ao) * 2;
            ldm4(qf[ka][m], sbase + off);
        }
    __syncthreads();

    float O[2][8][4] = {};
    float Ol[2][4] = {};               // l accumulators (ones-column mma)
    const uint32_t ones_b = (lane < 4) ? 0x3C003C00u : 0u;

    auto issue_kv = [&](int s, int t) {
        const half_t* srcs[2] = {Kg, Vg};
#pragma unroll
        for (int bi = 0; bi < 2; ++bi) {
            const half_t* g0 = srcs[bi] + gbase + (size_t)(t * 128) * D_;
#pragma unroll
            for (int it = 0; it < 8; ++it) {
                const int ch = tid + it * 128;
                const int r = ch >> 3, c8 = ch & 7;
                cp16(sbase + (s * 2 + bi) * SBUFB + (r * AST + c8 * 8) * 2,
                     g0 + (size_t)r * D_ + c8 * 8);
            }
        }
        CP_COMMIT();
    };

    issue_kv(0, 0);
    for (int t = 0; t < 16; ++t) {
        CP_WAIT0();
        __syncthreads();
        if (t + 1 < 16) issue_kv((t + 1) & 1, t + 1);
        const uint32_t kTile = sbase + (uint32_t)((t & 1) * 2) * SBUFB;
        const uint32_t vTile = kTile + SBUFB;

#pragma unroll
        for (int sub = 0; sub < 2; ++sub) {
            const int rofs = sub * 64;
#pragma unroll
            for (int h = 0; h < 2; ++h) {
                // ---- S = Q K^T for kv rows [rofs + h*32, +32) ----
                float S[2][4][4] = {};
#pragma unroll
                for (int ka = 0; ka < 4; ++ka)
#pragma unroll
                    for (int s = 0; s < 2; ++s) {
                        const int nb = 2 * h + s;
                        const uint32_t off =
                            (uint32_t)((rofs + nb * 16 + l7 + bro) * AST + ka * 16 + bko) * 2;
                        uint32_t kf[4];
                        ldm4(kf, kTile + off);
#pragma unroll
                        for (int m = 0; m < 2; ++m) {
                            mma_f16(S[m][2 * s],     qf[ka][m], kf[0], kf[1]);
                            mma_f16(S[m][2 * s + 1], qf[ka][m], kf[2], kf[3]);
                        }
                    }

                // ---- per k-chunk: p = 2^S, then PV ----
#pragma unroll
                for (int s = 0; s < 2; ++s) {
                    const int kt = 2 * h + s;
                    uint32_t pf[2][4];
#pragma unroll
                    for (int m = 0; m < 2; ++m) {
                        pf[m][0] = ex2_h2(pkh(S[m][2 * s][0],     S[m][2 * s][1]));
                        pf[m][1] = ex2_h2(pkh(S[m][2 * s][2],     S[m][2 * s][3]));
                        pf[m][2] = ex2_h2(pkh(S[m][2 * s + 1][0], S[m][2 * s + 1][1]));
                        pf[m][3] = ex2_h2(pkh(S[m][2 * s + 1][2], S[m][2 * s + 1][3]));
                    }
#pragma unroll
                    for (int nb = 0; nb < 4; ++nb) {
                        const uint32_t off =
                            (uint32_t)((rofs + kt * 16 + l15) * AST + nb * 16 + no) * 2;
                        uint32_t vf[4];
                        ldm4t(vf, vTile + off);
#pragma unroll
                        for (int m = 0; m < 2; ++m) {
                            mma_f16(O[m][2 * nb],     pf[m], vf[0], vf[1]);
                            mma_f16(O[m][2 * nb + 1], pf[m], vf[2], vf[3]);
                        }
                    }
#pragma unroll
                    for (int m = 0; m < 2; ++m)
                        mma_f16(Ol[m], pf[m], ones_b, ones_b);
                }
            }
        }
    }

    // ---- Epilogue: l from ones-column, normalize, store ----
    const int lr = lane >> 2, lc = lane & 3;
#pragma unroll
    for (int m = 0; m < 2; ++m) {
        const float l0 = __shfl_sync(0xffffffffu, Ol[m][0], lane & ~3);
        const float l1 = __shfl_sync(0xffffffffu, Ol[m][2], lane & ~3);
        const float inv0 = 1.f / l0, inv1 = 1.f / l1;
        const size_t rA = (size_t)bb * T_ + q0 + wq * 32 + m * 16 + lr;
        const size_t rB = rA + 8;
#pragma unroll
        for (int jn = 0; jn < 8; ++jn) {
            const int cg = hd * 64 + jn * 8 + lc * 2;
            *(uint32_t*)(Og + rA * D_ + cg) = pkh(O[m][jn][0] * inv0, O[m][jn][1] * inv0);
            *(uint32_t*)(Og + rB * D_ + cg) = pkh(O[m][jn][2] * inv1, O[m][jn][3] * inv1);
        }
    }
}

// ============================================================================
extern "C" void kernel_launch(void* const* d_in, const int* in_sizes, int n_in,
                              void* d_out, int out_size)
{
    (void)in_sizes; (void)n_in; (void)out_size;
    const float* q   = (const float*)d_in[0];
    const float* k   = (const float*)d_in[1];
    const float* v   = (const float*)d_in[2];
    const float* Wq  = (const float*)d_in[3];
    const float* b_q = (const float*)d_in[4];
    const float* Wk  = (const float*)d_in[5];
    const float* b_k = (const float*)d_in[6];
    const float* Wv  = (const float*)d_in[7];
    const float* b_v = (const float*)d_in[8];
    const float* Wo  = (const float*)d_in[9];
    const float* b_o = (const float*)d_in[10];
    float* out = (float*)d_out;

    half_t *in3, *qkv, *att, *w4;
    cudaGetSymbolAddress((void**)&in3, g_in3);
    cudaGetSymbolAddress((void**)&qkv, g_qkv);
    cudaGetSymbolAddress((void**)&att, g_att);
    cudaGetSymbolAddress((void**)&w4,  g_w4);

    cudaFuncSetAttribute(gemm_qkv, cudaFuncAttributeMaxDynamicSharedMemorySize, Q_SMEM);
    cudaFuncSetAttribute(gemm_out, cudaFuncAttributeMaxDynamicSharedMemorySize, G_SMEM);
    cudaFuncSetAttribute(attn_f16, cudaFuncAttributeMaxDynamicSharedMemorySize, A_SMEM);

    // Prep
    dim3 tgrid(32, 32, 4), tblk(32, 8);
    transpose_cvt4<<<tgrid, tblk>>>(Wq, Wk, Wv, Wo, w4);
    const int n4 = (int)(MD_ / 4);
    dim3 cgrid(n4 / 256, 3);
    tohalf3<<<cgrid, 256>>>((const float4*)q, (const float4*)k, (const float4*)v,
                            (uint2*)in3, n4);

    // Q/K/V projections: 128x128 tiles, 128 threads, warp 64x64, 3 CTAs/SM
    dim3 ggrid(D_ / 128, M_ / 128, 3);   // 8 x 64 x 3
    gemm_qkv<<<ggrid, 128, Q_SMEM>>>(in3, w4, b_q, b_k, b_v, qkv);

    // Attention (R12 winner)
    dim3 agrid(T_ / 128, H_, B_);
    attn_f16<<<agrid, 128, A_SMEM>>>(qkv + 0 * MD_, qkv + 1 * MD_, qkv + 2 * MD_, att);

    // Output projection -> fp32 (R12 proven 256-thread core)
    dim3 ogrid(D_ / 128, M_ / 128);
    gemm_out<<<ogrid, 256, G_SMEM>>>(att, w4 + 3 * DD_, b_o, out);
}